// round 10
// baseline (speedup 1.0000x reference)
#include <cuda_runtime.h>
#include <cuda_bf16.h>
#include <stdint.h>
#include <math.h>

#define N_NODES 10000
#define N_EDGES 160000
#define IN_F    16
#define D       512
#define N_GRAPHS 64
#define N_OUT   18
#define BN_EPS  1e-5f

// ---------------------------------------------------------------------------
// Scratch
// ---------------------------------------------------------------------------
__device__ float g_h[N_NODES * D];
__device__ float g_agg16[N_NODES * IN_F];
__device__ __nv_bfloat16 g_tHi[N_NODES * D];
__device__ __nv_bfloat16 g_tLo[N_NODES * D];
__device__ __nv_bfloat16 g_aHi[N_NODES * D];
__device__ __nv_bfloat16 g_aLo[N_NODES * D];
__device__ float g_bnsum[D];
__device__ float g_bnsq[D];
__device__ float g_pool[N_GRAPHS * D];
__device__ float g_cnt[N_GRAPHS];
__device__ __nv_bfloat16 g_Whi[9 * D * D];
__device__ __nv_bfloat16 g_Wlo[9 * D * D];
// CSR
__device__ int g_deg[N_NODES];
__device__ int g_rowptr[N_NODES + 1];
__device__ int g_colidx[N_EDGES];

typedef unsigned long long ull;

__device__ __forceinline__ void red_add_v4(float* p, float4 v) {
    asm volatile("red.global.add.v4.f32 [%0], {%1,%2,%3,%4};"
                 :: "l"(p), "f"(v.x), "f"(v.y), "f"(v.z), "f"(v.w) : "memory");
}
__device__ __forceinline__ uint32_t smem_u32(const void* p) {
    uint32_t a;
    asm("{ .reg .u64 t; cvta.to.shared.u64 t, %1; cvt.u32.u64 %0, t; }" : "=r"(a) : "l"(p));
    return a;
}
__device__ __forceinline__ void ldsm4(uint32_t* r, uint32_t p) {
    asm volatile("ldmatrix.sync.aligned.m8n8.x4.shared.b16 {%0,%1,%2,%3}, [%4];"
                 : "=r"(r[0]), "=r"(r[1]), "=r"(r[2]), "=r"(r[3]) : "r"(p));
}
__device__ __forceinline__ void mma16816(float* d, const uint32_t* a, const uint32_t* b) {
    asm volatile(
        "mma.sync.aligned.m16n8k16.row.col.f32.bf16.bf16.f32 "
        "{%0,%1,%2,%3}, {%4,%5,%6,%7}, {%8,%9}, {%0,%1,%2,%3};"
        : "+f"(d[0]), "+f"(d[1]), "+f"(d[2]), "+f"(d[3])
        : "r"(a[0]), "r"(a[1]), "r"(a[2]), "r"(a[3]), "r"(b[0]), "r"(b[1]));
}
__device__ __forceinline__ void cpasync16(uint32_t dst, const void* src, int validsz) {
    asm volatile("cp.async.ca.shared.global [%0], [%1], 16, %2;"
                 :: "r"(dst), "l"(src), "r"(validsz));
}
__device__ __forceinline__ void cp_commit() { asm volatile("cp.async.commit_group;" ::: "memory"); }
__device__ __forceinline__ void cp_wait1()  { asm volatile("cp.async.wait_group 1;" ::: "memory"); }
__device__ __forceinline__ void cp_wait0()  { asm volatile("cp.async.wait_group 0;" ::: "memory"); }

// SW64 swizzle: XOR byte bits[4:5] with bits[7:8].
__device__ __forceinline__ uint32_t swz(uint32_t b) { return b ^ ((b >> 3) & 0x30); }

__device__ __forceinline__ ull split_pack4(float4 v, ull& plo) {
    __nv_bfloat16 h0 = __float2bfloat16(v.x), h1 = __float2bfloat16(v.y);
    __nv_bfloat16 h2 = __float2bfloat16(v.z), h3 = __float2bfloat16(v.w);
    __nv_bfloat16 l0 = __float2bfloat16(v.x - __bfloat162float(h0));
    __nv_bfloat16 l1 = __float2bfloat16(v.y - __bfloat162float(h1));
    __nv_bfloat16 l2 = __float2bfloat16(v.z - __bfloat162float(h2));
    __nv_bfloat16 l3 = __float2bfloat16(v.w - __bfloat162float(h3));
    plo = (ull)__bfloat16_as_ushort(l0) | ((ull)__bfloat16_as_ushort(l1) << 16)
        | ((ull)__bfloat16_as_ushort(l2) << 32) | ((ull)__bfloat16_as_ushort(l3) << 48);
    return (ull)__bfloat16_as_ushort(h0) | ((ull)__bfloat16_as_ushort(h1) << 16)
         | ((ull)__bfloat16_as_ushort(h2) << 32) | ((ull)__bfloat16_as_ushort(h3) << 48);
}

// ---------------------------------------------------------------------------
// Utility kernels
// ---------------------------------------------------------------------------
__global__ void k_copy4(float* __restrict__ dst, const float* __restrict__ src, int n4) {
    int i = blockIdx.x * blockDim.x + threadIdx.x;
    if (i < n4) ((float4*)dst)[i] = ((const float4*)src)[i];
}
__global__ void k_zero_bn() {
    int i = blockIdx.x * blockDim.x + threadIdx.x;
    if (i < D) { g_bnsum[i] = 0.f; g_bnsq[i] = 0.f; }
}
__global__ void k_zero_pool() {
    int i = blockIdx.x * blockDim.x + threadIdx.x;
    if (i < N_GRAPHS * D) g_pool[i] = 0.f;
    if (i < N_GRAPHS) g_cnt[i] = 0.f;
}

// ---------------------------------------------------------------------------
// CSR build
// ---------------------------------------------------------------------------
__global__ void k_zero_deg() {
    int i = blockIdx.x * blockDim.x + threadIdx.x;
    if (i < N_NODES) g_deg[i] = 0;
}
__global__ void k_deg(const int* __restrict__ dst) {
    int e = blockIdx.x * blockDim.x + threadIdx.x;
    if (e < N_EDGES) atomicAdd(&g_deg[dst[e]], 1);
}
__global__ void k_scan() {
    __shared__ int ssum[1024];
    int t = threadIdx.x;
    int base = t * 10;
    int loc[10];
    int s = 0;
#pragma unroll
    for (int i = 0; i < 10; i++) {
        int idx = base + i;
        int v = (idx < N_NODES) ? g_deg[idx] : 0;
        loc[i] = s; s += v;
    }
    ssum[t] = s;
    __syncthreads();
    for (int off = 1; off < 1024; off <<= 1) {
        int add = (t >= off) ? ssum[t - off] : 0;
        __syncthreads();
        ssum[t] += add;
        __syncthreads();
    }
    int excl = ssum[t] - s;
#pragma unroll
    for (int i = 0; i < 10; i++) {
        int idx = base + i;
        if (idx < N_NODES) { g_rowptr[idx] = excl + loc[i]; g_deg[idx] = 0; }
    }
    if (t == 0) g_rowptr[N_NODES] = N_EDGES;
}
__global__ void k_fill(const int* __restrict__ src, const int* __restrict__ dst) {
    int e = blockIdx.x * blockDim.x + threadIdx.x;
    if (e >= N_EDGES) return;
    int d = dst[e];
    int p = atomicAdd(&g_deg[d], 1);
    g_colidx[g_rowptr[d] + p] = src[e];
}

// ---------------------------------------------------------------------------
// Weight convert + transpose: out[m][n][k] = split(W_m[k][n])
// ---------------------------------------------------------------------------
__global__ void k_convW(const float* __restrict__ W1b, const float* __restrict__ Wa,
                        const float* __restrict__ Wb) {
    __shared__ float tile[32][33];
    int m = blockIdx.z;
    const float* W = (m == 0) ? W1b
                   : ((m & 1) ? Wa + (size_t)((m - 1) >> 1) * D * D
                              : Wb + (size_t)((m - 2) >> 1) * D * D);
    int tx = threadIdx.x, ty = threadIdx.y;
    int n0 = blockIdx.x * 32, k0 = blockIdx.y * 32;
#pragma unroll
    for (int j = 0; j < 32; j += 8)
        tile[ty + j][tx] = W[(k0 + ty + j) * D + n0 + tx];
    __syncthreads();
#pragma unroll
    for (int j = 0; j < 32; j += 8) {
        float v = tile[tx][ty + j];
        int n = n0 + ty + j, k = k0 + tx;
        __nv_bfloat16 hi = __float2bfloat16(v);
        __nv_bfloat16 lo = __float2bfloat16(v - __bfloat162float(hi));
        size_t o = (size_t)m * D * D + (size_t)n * D + k;
        g_Whi[o] = hi;
        g_Wlo[o] = lo;
    }
}

// ---------------------------------------------------------------------------
// Layer-1 aggregation + small GEMM (IN_F=16), emits split bf16 + relu
// ---------------------------------------------------------------------------
__global__ void k_scatter16(const float* __restrict__ x,
                            const int* __restrict__ src, const int* __restrict__ dst) {
    int idx = blockIdx.x * blockDim.x + threadIdx.x;
    if (idx >= N_EDGES * 4) return;
    int e = idx >> 2;
    int g = (idx & 3) << 2;
    int s = src[e], d = dst[e];
    float4 v = *(const float4*)&x[s * IN_F + g];
    red_add_v4(&g_agg16[d * IN_F + g], v);
}

__global__ void k_gemm16(const float* __restrict__ W, const float* __restrict__ bias) {
    int idx = blockIdx.x * blockDim.x + threadIdx.x;
    if (idx >= N_NODES * (D / 4)) return;
    int n = idx >> 7;
    int c = (idx & 127) << 2;
    float4 acc = *(const float4*)&bias[c];
    const float* arow = &g_agg16[n * IN_F];
#pragma unroll
    for (int k = 0; k < IN_F; k++) {
        float a = arow[k];
        float4 w = *(const float4*)&W[k * D + c];
        acc.x += a * w.x; acc.y += a * w.y; acc.z += a * w.z; acc.w += a * w.w;
    }
    acc.x = fmaxf(acc.x, 0.f); acc.y = fmaxf(acc.y, 0.f);
    acc.z = fmaxf(acc.z, 0.f); acc.w = fmaxf(acc.w, 0.f);
    ull pl;
    ull ph = split_pack4(acc, pl);
    *(ull*)&g_tHi[n * D + c] = ph;
    *(ull*)&g_tLo[n * D + c] = pl;
}

// ---------------------------------------------------------------------------
// CSR gather + fused BN-apply + hi/lo split.
// ---------------------------------------------------------------------------
__global__ __launch_bounds__(256)
void k_gather_bn(const float* __restrict__ h,
                 const float* __restrict__ gamma, const float* __restrict__ beta,
                 __nv_bfloat16* __restrict__ Hi, __nv_bfloat16* __restrict__ Lo) {
    int gw = (blockIdx.x * 256 + threadIdx.x) >> 5;
    if (gw >= N_NODES * 4) return;
    int lane = threadIdx.x & 31;
    int n = gw >> 2;
    int c = ((gw & 3) << 7) + lane * 4;

    float4 acc = *(const float4*)&h[(size_t)n * D + c];
    int e0 = g_rowptr[n], e1 = g_rowptr[n + 1];
    int e = e0;
    for (; e + 2 <= e1; e += 2) {
        int s0 = g_colidx[e], s1 = g_colidx[e + 1];
        float4 v0 = *(const float4*)&h[(size_t)s0 * D + c];
        float4 v1 = *(const float4*)&h[(size_t)s1 * D + c];
        acc.x += v0.x + v1.x; acc.y += v0.y + v1.y;
        acc.z += v0.z + v1.z; acc.w += v0.w + v1.w;
    }
    if (e < e1) {
        int s0 = g_colidx[e];
        float4 v0 = *(const float4*)&h[(size_t)s0 * D + c];
        acc.x += v0.x; acc.y += v0.y; acc.z += v0.z; acc.w += v0.w;
    }
    float cnt = (float)(e1 - e0 + 1);
    const float invN = 1.0f / N_NODES;
    float4 bs = *(const float4*)&g_bnsum[c];
    float4 bq = *(const float4*)&g_bnsq[c];
    float4 gm = *(const float4*)&gamma[c];
    float4 bt = *(const float4*)&beta[c];
    float m0 = bs.x * invN, m1 = bs.y * invN, m2 = bs.z * invN, m3 = bs.w * invN;
    float s0 = gm.x * rsqrtf(bq.x * invN - m0 * m0 + BN_EPS);
    float s1 = gm.y * rsqrtf(bq.y * invN - m1 * m1 + BN_EPS);
    float s2 = gm.z * rsqrtf(bq.z * invN - m2 * m2 + BN_EPS);
    float s3 = gm.w * rsqrtf(bq.w * invN - m3 * m3 + BN_EPS);
    float4 o;
    o.x = s0 * acc.x + cnt * (bt.x - s0 * m0);
    o.y = s1 * acc.y + cnt * (bt.y - s1 * m1);
    o.z = s2 * acc.z + cnt * (bt.z - s2 * m2);
    o.w = s3 * acc.w + cnt * (bt.w - s3 * m3);
    ull pl;
    ull ph = split_pack4(o, pl);
    *(ull*)&Hi[(size_t)n * D + c] = ph;
    *(ull*)&Lo[(size_t)n * D + c] = pl;
}

// ---------------------------------------------------------------------------
// HMMA GEMM: BM=64, BN=128, BK=32, 64 threads (2 warps, 64x64 warp tile),
// SW64-swizzled smem, cp.async double-buffered, 4 CTAs/SM.
// 3-term split: Ahi*Bhi + Ahi*Blo + Alo*Bhi, fp32 accum.
// mode 0: out f32 + relu + fused BN stats; mode 1: out split bf16 + relu.
// ---------------------------------------------------------------------------
#define BM 64
#define BN 128
#define BK 32
#define A_ARR 4096                 // 64 rows * 64 B
#define B_ARR 8192                 // 128 rows * 64 B
#define STG_B (2 * A_ARR + 2 * B_ARR)   // 24576
#define GEMM_SMEM (2 * STG_B)           // 49152

__global__ __launch_bounds__(64, 4)
void k_gemm512_mma(const __nv_bfloat16* __restrict__ Ahi,
                   const __nv_bfloat16* __restrict__ Alo,
                   const __nv_bfloat16* __restrict__ Bthi,
                   const __nv_bfloat16* __restrict__ Btlo,
                   const float* __restrict__ bias,
                   float* __restrict__ Cf,
                   __nv_bfloat16* __restrict__ Chi,
                   __nv_bfloat16* __restrict__ Clo,
                   int M, int mode) {
    extern __shared__ char sm[];
    const uint32_t sbase = smem_u32(sm);

    const int tid = threadIdx.x;
    const int lane = tid & 31;
    const int wn = tid >> 5;       // 2 warps over N (64 cols each)
    const int rowBase = blockIdx.x * BM;
    const int colBase = blockIdx.y * BN;

    // producer coords: 16 rows per round, 4x16B per row
    const int rp = tid >> 2, cp = tid & 3;

    float acc[4][8][4];
#pragma unroll
    for (int mi = 0; mi < 4; mi++)
#pragma unroll
        for (int ni = 0; ni < 8; ni++)
#pragma unroll
            for (int j = 0; j < 4; j++) acc[mi][ni][j] = 0.f;

#define PREFETCH(kc_, s_)                                                           \
    {                                                                               \
        const int k0_ = (kc_) * BK;                                                 \
        const uint32_t sb_ = sbase + (s_) * STG_B;                                  \
        _Pragma("unroll")                                                           \
        for (int j_ = 0; j_ < 4; j_++) {                                            \
            int r_ = rp + j_ * 16;                                                  \
            int ok_ = (rowBase + r_ < M) ? 16 : 0;                                  \
            uint32_t so_ = swz((uint32_t)(r_ * 64 + cp * 16));                      \
            cpasync16(sb_ + so_, &Ahi[(size_t)(rowBase + r_) * D + k0_ + cp * 8], ok_); \
            cpasync16(sb_ + A_ARR + so_, &Alo[(size_t)(rowBase + r_) * D + k0_ + cp * 8], ok_); \
        }                                                                           \
        _Pragma("unroll")                                                           \
        for (int j_ = 0; j_ < 8; j_++) {                                            \
            int r_ = rp + j_ * 16;                                                  \
            uint32_t so_ = swz((uint32_t)(r_ * 64 + cp * 16));                      \
            cpasync16(sb_ + 2 * A_ARR + so_, &Bthi[(size_t)(colBase + r_) * D + k0_ + cp * 8], 16); \
            cpasync16(sb_ + 2 * A_ARR + B_ARR + so_, &Btlo[(size_t)(colBase + r_) * D + k0_ + cp * 8], 16); \
        }                                                                           \
        cp_commit();                                                                \
    }

    PREFETCH(0, 0);

    for (int kc = 0; kc < D / BK; kc++) {
        const int s = kc & 1;
        if (kc + 1 < D / BK) {
            PREFETCH(kc + 1, s ^ 1);
            cp_wait1();
        } else {
            cp_wait0();
        }
        __syncthreads();

        const uint32_t sb = sbase + s * STG_B;
        const uint32_t aHiB = sb, aLoB = sb + A_ARR;
        const uint32_t bHiB = sb + 2 * A_ARR, bLoB = bHiB + B_ARR;

#pragma unroll
        for (int ks = 0; ks < 2; ks++) {
            const int kk = ks * 16;
            uint32_t ahi[4][4], alo[4][4];
#pragma unroll
            for (int mi = 0; mi < 4; mi++) {
                int row = mi * 16 + (lane & 15);
                uint32_t off = swz((uint32_t)(row * 64 + kk * 2 + (lane >> 4) * 16));
                ldsm4(ahi[mi], aHiB + off);
                ldsm4(alo[mi], aLoB + off);
            }
            int brow = wn * 64 + (lane & 7) + ((lane >> 4) << 3);
            int bcolb = kk * 2 + ((lane >> 3) & 1) * 16;
#pragma unroll
            for (int np = 0; np < 4; np++) {
                uint32_t bhi4[4], blo4[4];
                uint32_t off = swz((uint32_t)((brow + np * 16) * 64 + bcolb));
                ldsm4(bhi4, bHiB + off);
                ldsm4(blo4, bLoB + off);
#pragma unroll
                for (int mi = 0; mi < 4; mi++) {
                    mma16816(acc[mi][2 * np + 0], ahi[mi], bhi4 + 0);
                    mma16816(acc[mi][2 * np + 0], ahi[mi], blo4 + 0);
                    mma16816(acc[mi][2 * np + 0], alo[mi], bhi4 + 0);
                    mma16816(acc[mi][2 * np + 1], ahi[mi], bhi4 + 2);
                    mma16816(acc[mi][2 * np + 1], ahi[mi], blo4 + 2);
                    mma16816(acc[mi][2 * np + 1], alo[mi], bhi4 + 2);
                }
            }
        }
        __syncthreads();
    }
#undef PREFETCH

    // ---- epilogue
    if (mode == 0) {
        float* scol = (float*)sm;          // 128 floats
        float* qcol = scol + 128;          // 128 floats
        scol[tid] = 0.f; qcol[tid] = 0.f;
        scol[tid + 64] = 0.f; qcol[tid + 64] = 0.f;
        __syncthreads();
#pragma unroll
        for (int ni = 0; ni < 8; ni++) {
            int col = colBase + wn * 64 + ni * 8 + (lane & 3) * 2;
            float b0 = bias[col], b1 = bias[col + 1];
            float s0 = 0.f, q0 = 0.f, s1 = 0.f, q1 = 0.f;
#pragma unroll
            for (int mi = 0; mi < 4; mi++) {
                int row0 = rowBase + mi * 16 + (lane >> 2);
                int row1 = row0 + 8;
                float v00 = fmaxf(acc[mi][ni][0] + b0, 0.f);
                float v01 = fmaxf(acc[mi][ni][1] + b1, 0.f);
                float v10 = fmaxf(acc[mi][ni][2] + b0, 0.f);
                float v11 = fmaxf(acc[mi][ni][3] + b1, 0.f);
                if (row0 < M) {
                    *(float2*)&Cf[(size_t)row0 * D + col] = make_float2(v00, v01);
                    s0 += v00; q0 += v00 * v00; s1 += v01; q1 += v01 * v01;
                }
                if (row1 < M) {
                    *(float2*)&Cf[(size_t)row1 * D + col] = make_float2(v10, v11);
                    s0 += v10; q0 += v10 * v10; s1 += v11; q1 += v11 * v11;
                }
            }
#pragma unroll
            for (int o = 4; o < 32; o <<= 1) {
                s0 += __shfl_xor_sync(0xffffffffu, s0, o);
                q0 += __shfl_xor_sync(0xffffffffu, q0, o);
                s1 += __shfl_xor_sync(0xffffffffu, s1, o);
                q1 += __shfl_xor_sync(0xffffffffu, q1, o);
            }
            if (lane < 4) {
                int lc = wn * 64 + ni * 8 + lane * 2;
                atomicAdd(&scol[lc], s0);
                atomicAdd(&qcol[lc], q0);
                atomicAdd(&scol[lc + 1], s1);
                atomicAdd(&qcol[lc + 1], q1);
            }
        }
        __syncthreads();
        atomicAdd(&g_bnsum[colBase + tid], scol[tid]);
        atomicAdd(&g_bnsq[colBase + tid], qcol[tid]);
        atomicAdd(&g_bnsum[colBase + tid + 64], scol[tid + 64]);
        atomicAdd(&g_bnsq[colBase + tid + 64], qcol[tid + 64]);
    } else {
#pragma unroll
        for (int mi = 0; mi < 4; mi++) {
            int row0 = rowBase + mi * 16 + (lane >> 2);
            int row1 = row0 + 8;
#pragma unroll
            for (int ni = 0; ni < 8; ni++) {
                int col = colBase + wn * 64 + ni * 8 + (lane & 3) * 2;
                float b0 = bias[col], b1 = bias[col + 1];
                float v00 = fmaxf(acc[mi][ni][0] + b0, 0.f);
                float v01 = fmaxf(acc[mi][ni][1] + b1, 0.f);
                float v10 = fmaxf(acc[mi][ni][2] + b0, 0.f);
                float v11 = fmaxf(acc[mi][ni][3] + b1, 0.f);
                __nv_bfloat16 h0 = __float2bfloat16(v00), h1 = __float2bfloat16(v01);
                __nv_bfloat16 h2 = __float2bfloat16(v10), h3 = __float2bfloat16(v11);
                __nv_bfloat16 l0 = __float2bfloat16(v00 - __bfloat162float(h0));
                __nv_bfloat16 l1 = __float2bfloat16(v01 - __bfloat162float(h1));
                __nv_bfloat16 l2 = __float2bfloat16(v10 - __bfloat162float(h2));
                __nv_bfloat16 l3 = __float2bfloat16(v11 - __bfloat162float(h3));
                if (row0 < M) {
                    *(uint32_t*)&Chi[(size_t)row0 * D + col] =
                        (uint32_t)__bfloat16_as_ushort(h0) | ((uint32_t)__bfloat16_as_ushort(h1) << 16);
                    *(uint32_t*)&Clo[(size_t)row0 * D + col] =
                        (uint32_t)__bfloat16_as_ushort(l0) | ((uint32_t)__bfloat16_as_ushort(l1) << 16);
                }
                if (row1 < M) {
                    *(uint32_t*)&Chi[(size_t)row1 * D + col] =
                        (uint32_t)__bfloat16_as_ushort(h2) | ((uint32_t)__bfloat16_as_ushort(h3) << 16);
                    *(uint32_t*)&Clo[(size_t)row1 * D + col] =
                        (uint32_t)__bfloat16_as_ushort(l2) | ((uint32_t)__bfloat16_as_ushort(l3) << 16);
                }
            }
        }
    }
}

// ---------------------------------------------------------------------------
// Pool + head (BN affine applied to pooled means inside k_head)
// ---------------------------------------------------------------------------
__global__ void k_poolscatter(const float* __restrict__ h, const int* __restrict__ batch) {
    int idx = blockIdx.x * blockDim.x + threadIdx.x;
    if (idx >= N_NODES * (D / 4)) return;
    int n = idx >> 7;
    int g = (idx & 127) << 2;
    int b = batch[n];
    float4 v = *(const float4*)&h[n * D + g];
    red_add_v4(&g_pool[b * D + g], v);
}
__global__ void k_count(const int* __restrict__ batch) {
    int n = blockIdx.x * blockDim.x + threadIdx.x;
    if (n < N_NODES) atomicAdd(&g_cnt[batch[n]], 1.0f);
}
__global__ void k_head(const float* __restrict__ Wfc, const float* __restrict__ bfc,
                       const float* __restrict__ Wlog, const float* __restrict__ blog,
                       const float* __restrict__ gamma, const float* __restrict__ beta,
                       float* __restrict__ out) {
    __shared__ float sp[D];
    __shared__ float sf[D];
    int g = blockIdx.x;
    int t = threadIdx.x;
    float cnt = g_cnt[g];
    float invc = 1.0f / fmaxf(cnt, 1.0f);
    const float invN = 1.0f / N_NODES;
    float mean = g_bnsum[t] * invN;
    float var = g_bnsq[t] * invN - mean * mean;
    float sc = gamma[t] * rsqrtf(var + BN_EPS);
    sp[t] = sc * (g_pool[g * D + t] * invc) + (cnt * invc) * (beta[t] - sc * mean);
    __syncthreads();
    float f = bfc[t];
    for (int k = 0; k < D; k++) f += sp[k] * Wfc[k * D + t];
    sf[t] = tanhf(f);
    __syncthreads();
    if (t < N_OUT) {
        float l = blog[t];
        for (int k = 0; k < D; k++) l += sf[k] * Wlog[k * N_OUT + t];
        out[g * N_OUT + t] = l;
    }
}

// ---------------------------------------------------------------------------
// Launcher
// ---------------------------------------------------------------------------
extern "C" void kernel_launch(void* const* d_in, const int* in_sizes, int n_in,
                              void* d_out, int out_size) {
    const float* x     = (const float*)d_in[0];
    const int*   ei    = (const int*)d_in[1];
    const int*   batch = (const int*)d_in[2];
    const float* W1a   = (const float*)d_in[3];
    const float* b1a   = (const float*)d_in[4];
    const float* W1b   = (const float*)d_in[5];
    const float* b1b   = (const float*)d_in[6];
    const float* Wa    = (const float*)d_in[7];
    const float* ba    = (const float*)d_in[8];
    const float* Wb    = (const float*)d_in[9];
    const float* bb    = (const float*)d_in[10];
    const float* bn_g  = (const float*)d_in[11];
    const float* bn_b  = (const float*)d_in[12];
    const float* Wfc   = (const float*)d_in[13];
    const float* bfc   = (const float*)d_in[14];
    const float* Wlog  = (const float*)d_in[15];
    const float* blog  = (const float*)d_in[16];
    float* out = (float*)d_out;

    const int* src = ei;
    const int* dst = ei + N_EDGES;

    float *h, *agg16;
    __nv_bfloat16 *whi, *wlo, *thi, *tlo, *ahi, *alo;
    cudaGetSymbolAddress((void**)&h,     g_h);
    cudaGetSymbolAddress((void**)&agg16, g_agg16);
    cudaGetSymbolAddress((void**)&whi,   g_Whi);
    cudaGetSymbolAddress((void**)&wlo,   g_Wlo);
    cudaGetSymbolAddress((void**)&thi,   g_tHi);
    cudaGetSymbolAddress((void**)&tlo,   g_tLo);
    cudaGetSymbolAddress((void**)&ahi,   g_aHi);
    cudaGetSymbolAddress((void**)&alo,   g_aLo);

    cudaFuncSetAttribute(k_gemm512_mma, cudaFuncAttributeMaxDynamicSharedMemorySize, GEMM_SMEM);

    const int TB = 256;
    dim3 gemmGrid((N_NODES + BM - 1) / BM, D / BN);   // (157, 4)
    const size_t DD = (size_t)D * D;

    // CSR build + weight pre-convert
    k_zero_deg<<<(N_NODES + TB - 1) / TB, TB>>>();
    k_deg<<<(N_EDGES + TB - 1) / TB, TB>>>(dst);
    k_scan<<<1, 1024>>>();
    k_fill<<<(N_EDGES + TB - 1) / TB, TB>>>(src, dst);
    k_convW<<<dim3(16, 16, 9), dim3(32, 8)>>>(W1b, Wa, Wb);

    // ---- layer 1 ----
    k_copy4<<<(N_NODES * IN_F / 4 + TB - 1) / TB, TB>>>(agg16, x, N_NODES * IN_F / 4);
    k_scatter16<<<(N_EDGES * 4 + TB - 1) / TB, TB>>>(x, src, dst);
    k_gemm16<<<(N_NODES * 128 + TB - 1) / TB, TB>>>(W1a, b1a);
    k_zero_bn<<<2, 256>>>();
    k_gemm512_mma<<<gemmGrid, 64, GEMM_SMEM>>>(thi, tlo, whi, wlo, b1b, h,
                                               ((__nv_bfloat16*)0), ((__nv_bfloat16*)0),
                                               N_NODES, 0);

    // ---- layers 2..5 ----
    for (int i = 0; i < 4; i++) {
        k_gather_bn<<<(N_NODES * 4 * 32 + TB - 1) / TB, TB>>>(h, bn_g + i * D, bn_b + i * D,
                                                              ahi, alo);
        k_gemm512_mma<<<gemmGrid, 64, GEMM_SMEM>>>(ahi, alo,
                                                   whi + (size_t)(1 + 2 * i) * DD,
                                                   wlo + (size_t)(1 + 2 * i) * DD,
                                                   ba + i * D, ((float*)0), thi, tlo,
                                                   N_NODES, 1);
        k_zero_bn<<<2, 256>>>();
        k_gemm512_mma<<<gemmGrid, 64, GEMM_SMEM>>>(thi, tlo,
                                                   whi + (size_t)(2 + 2 * i) * DD,
                                                   wlo + (size_t)(2 + 2 * i) * DD,
                                                   bb + i * D, h,
                                                   ((__nv_bfloat16*)0), ((__nv_bfloat16*)0),
                                                   N_NODES, 0);
    }

    // ---- pooling + head (BN5 applied on pooled means) ----
    k_zero_pool<<<(N_GRAPHS * D + TB - 1) / TB, TB>>>();
    k_poolscatter<<<(N_NODES * 128 + TB - 1) / TB, TB>>>(h, batch);
    k_count<<<(N_NODES + TB - 1) / TB, TB>>>(batch);
    k_head<<<N_GRAPHS, D>>>(Wfc, bfc, Wlog, blog, bn_g + 4 * D, bn_b + 4 * D, out);
}

// round 11
// speedup vs baseline: 1.6978x; 1.6978x over previous
#include <cuda_runtime.h>
#include <cuda_bf16.h>
#include <stdint.h>
#include <math.h>

#define N_NODES 10000
#define N_EDGES 160000
#define IN_F    16
#define D       512
#define N_GRAPHS 64
#define N_OUT   18
#define BN_EPS  1e-5f

// ---------------------------------------------------------------------------
// Scratch
// ---------------------------------------------------------------------------
__device__ float g_h[N_NODES * D];
__device__ float g_agg16[N_NODES * IN_F];
__device__ __nv_bfloat16 g_tHi[N_NODES * D];
__device__ __nv_bfloat16 g_tLo[N_NODES * D];
__device__ __nv_bfloat16 g_aHi[N_NODES * D];
__device__ __nv_bfloat16 g_aLo[N_NODES * D];
__device__ float g_bnsum[D];
__device__ float g_bnsq[D];
__device__ float g_pool[N_GRAPHS * D];
__device__ float g_cnt[N_GRAPHS];
__device__ __nv_bfloat16 g_Whi[9 * D * D];
__device__ __nv_bfloat16 g_Wlo[9 * D * D];
// CSR
__device__ int g_deg[N_NODES];
__device__ int g_rowptr[N_NODES + 1];
__device__ int g_colidx[N_EDGES];

typedef unsigned long long ull;

__device__ __forceinline__ void red_add_v4(float* p, float4 v) {
    asm volatile("red.global.add.v4.f32 [%0], {%1,%2,%3,%4};"
                 :: "l"(p), "f"(v.x), "f"(v.y), "f"(v.z), "f"(v.w) : "memory");
}
__device__ __forceinline__ uint32_t smem_u32(const void* p) {
    uint32_t a;
    asm("{ .reg .u64 t; cvta.to.shared.u64 t, %1; cvt.u32.u64 %0, t; }" : "=r"(a) : "l"(p));
    return a;
}
__device__ __forceinline__ void ldsm4(uint32_t* r, uint32_t p) {
    asm volatile("ldmatrix.sync.aligned.m8n8.x4.shared.b16 {%0,%1,%2,%3}, [%4];"
                 : "=r"(r[0]), "=r"(r[1]), "=r"(r[2]), "=r"(r[3]) : "r"(p));
}
__device__ __forceinline__ void mma16816(float* d, const uint32_t* a, const uint32_t* b) {
    asm volatile(
        "mma.sync.aligned.m16n8k16.row.col.f32.bf16.bf16.f32 "
        "{%0,%1,%2,%3}, {%4,%5,%6,%7}, {%8,%9}, {%0,%1,%2,%3};"
        : "+f"(d[0]), "+f"(d[1]), "+f"(d[2]), "+f"(d[3])
        : "r"(a[0]), "r"(a[1]), "r"(a[2]), "r"(a[3]), "r"(b[0]), "r"(b[1]));
}
__device__ __forceinline__ void cpasync16(uint32_t dst, const void* src, int validsz) {
    asm volatile("cp.async.ca.shared.global [%0], [%1], 16, %2;"
                 :: "r"(dst), "l"(src), "r"(validsz));
}
__device__ __forceinline__ void cp_commit() { asm volatile("cp.async.commit_group;" ::: "memory"); }
__device__ __forceinline__ void cp_wait1()  { asm volatile("cp.async.wait_group 1;" ::: "memory"); }
__device__ __forceinline__ void cp_wait0()  { asm volatile("cp.async.wait_group 0;" ::: "memory"); }

// SW64 swizzle: XOR byte bits[4:5] with bits[7:8].
__device__ __forceinline__ uint32_t swz(uint32_t b) { return b ^ ((b >> 3) & 0x30); }

__device__ __forceinline__ ull split_pack4(float4 v, ull& plo) {
    __nv_bfloat16 h0 = __float2bfloat16(v.x), h1 = __float2bfloat16(v.y);
    __nv_bfloat16 h2 = __float2bfloat16(v.z), h3 = __float2bfloat16(v.w);
    __nv_bfloat16 l0 = __float2bfloat16(v.x - __bfloat162float(h0));
    __nv_bfloat16 l1 = __float2bfloat16(v.y - __bfloat162float(h1));
    __nv_bfloat16 l2 = __float2bfloat16(v.z - __bfloat162float(h2));
    __nv_bfloat16 l3 = __float2bfloat16(v.w - __bfloat162float(h3));
    plo = (ull)__bfloat16_as_ushort(l0) | ((ull)__bfloat16_as_ushort(l1) << 16)
        | ((ull)__bfloat16_as_ushort(l2) << 32) | ((ull)__bfloat16_as_ushort(l3) << 48);
    return (ull)__bfloat16_as_ushort(h0) | ((ull)__bfloat16_as_ushort(h1) << 16)
         | ((ull)__bfloat16_as_ushort(h2) << 32) | ((ull)__bfloat16_as_ushort(h3) << 48);
}

// ---------------------------------------------------------------------------
// Utility kernels
// ---------------------------------------------------------------------------
__global__ void k_copy4(float* __restrict__ dst, const float* __restrict__ src, int n4) {
    int i = blockIdx.x * blockDim.x + threadIdx.x;
    if (i < n4) ((float4*)dst)[i] = ((const float4*)src)[i];
}

// ---------------------------------------------------------------------------
// CSR build
// ---------------------------------------------------------------------------
__global__ void k_zero_deg() {
    int i = blockIdx.x * blockDim.x + threadIdx.x;
    if (i < N_NODES) g_deg[i] = 0;
}
__global__ void k_deg(const int* __restrict__ dst) {
    int e = blockIdx.x * blockDim.x + threadIdx.x;
    if (e < N_EDGES) atomicAdd(&g_deg[dst[e]], 1);
}
__global__ void k_scan() {
    __shared__ int ssum[1024];
    int t = threadIdx.x;
    int base = t * 10;
    int loc[10];
    int s = 0;
#pragma unroll
    for (int i = 0; i < 10; i++) {
        int idx = base + i;
        int v = (idx < N_NODES) ? g_deg[idx] : 0;
        loc[i] = s; s += v;
    }
    ssum[t] = s;
    __syncthreads();
    for (int off = 1; off < 1024; off <<= 1) {
        int add = (t >= off) ? ssum[t - off] : 0;
        __syncthreads();
        ssum[t] += add;
        __syncthreads();
    }
    int excl = ssum[t] - s;
#pragma unroll
    for (int i = 0; i < 10; i++) {
        int idx = base + i;
        if (idx < N_NODES) { g_rowptr[idx] = excl + loc[i]; g_deg[idx] = 0; }
    }
    if (t == 0) g_rowptr[N_NODES] = N_EDGES;
}
__global__ void k_fill(const int* __restrict__ src, const int* __restrict__ dst) {
    int e = blockIdx.x * blockDim.x + threadIdx.x;
    if (e >= N_EDGES) return;
    int d = dst[e];
    int p = atomicAdd(&g_deg[d], 1);
    g_colidx[g_rowptr[d] + p] = src[e];
}

// ---------------------------------------------------------------------------
// Weight convert + transpose: out[m][n][k] = split(W_m[k][n])
// ---------------------------------------------------------------------------
__global__ void k_convW(const float* __restrict__ W1b, const float* __restrict__ Wa,
                        const float* __restrict__ Wb) {
    __shared__ float tile[32][33];
    int m = blockIdx.z;
    const float* W = (m == 0) ? W1b
                   : ((m & 1) ? Wa + (size_t)((m - 1) >> 1) * D * D
                              : Wb + (size_t)((m - 2) >> 1) * D * D);
    int tx = threadIdx.x, ty = threadIdx.y;
    int n0 = blockIdx.x * 32, k0 = blockIdx.y * 32;
#pragma unroll
    for (int j = 0; j < 32; j += 8)
        tile[ty + j][tx] = W[(k0 + ty + j) * D + n0 + tx];
    __syncthreads();
#pragma unroll
    for (int j = 0; j < 32; j += 8) {
        float v = tile[tx][ty + j];
        int n = n0 + ty + j, k = k0 + tx;
        __nv_bfloat16 hi = __float2bfloat16(v);
        __nv_bfloat16 lo = __float2bfloat16(v - __bfloat162float(hi));
        size_t o = (size_t)m * D * D + (size_t)n * D + k;
        g_Whi[o] = hi;
        g_Wlo[o] = lo;
    }
}

// ---------------------------------------------------------------------------
// Layer-1 aggregation + small GEMM (IN_F=16), emits split bf16 + relu.
// Block 0 also zeroes the BN counters (safe: stats are accumulated by the
// NEXT kernel, the mode-0 GEMM).
// ---------------------------------------------------------------------------
__global__ void k_scatter16(const float* __restrict__ x,
                            const int* __restrict__ src, const int* __restrict__ dst) {
    int idx = blockIdx.x * blockDim.x + threadIdx.x;
    if (idx >= N_EDGES * 4) return;
    int e = idx >> 2;
    int g = (idx & 3) << 2;
    int s = src[e], d = dst[e];
    float4 v = *(const float4*)&x[s * IN_F + g];
    red_add_v4(&g_agg16[d * IN_F + g], v);
}

__global__ void k_gemm16(const float* __restrict__ W, const float* __restrict__ bias) {
    int idx = blockIdx.x * blockDim.x + threadIdx.x;
    if (blockIdx.x == 0 && threadIdx.x < 128) {
        ((float4*)g_bnsum)[threadIdx.x] = make_float4(0.f, 0.f, 0.f, 0.f);
        ((float4*)g_bnsq)[threadIdx.x] = make_float4(0.f, 0.f, 0.f, 0.f);
    }
    if (idx >= N_NODES * (D / 4)) return;
    int n = idx >> 7;
    int c = (idx & 127) << 2;
    float4 acc = *(const float4*)&bias[c];
    const float* arow = &g_agg16[n * IN_F];
#pragma unroll
    for (int k = 0; k < IN_F; k++) {
        float a = arow[k];
        float4 w = *(const float4*)&W[k * D + c];
        acc.x += a * w.x; acc.y += a * w.y; acc.z += a * w.z; acc.w += a * w.w;
    }
    acc.x = fmaxf(acc.x, 0.f); acc.y = fmaxf(acc.y, 0.f);
    acc.z = fmaxf(acc.z, 0.f); acc.w = fmaxf(acc.w, 0.f);
    ull pl;
    ull ph = split_pack4(acc, pl);
    *(ull*)&g_tHi[n * D + c] = ph;
    *(ull*)&g_tLo[n * D + c] = pl;
}

// ---------------------------------------------------------------------------
// CSR gather + fused BN-apply + hi/lo split.
// ---------------------------------------------------------------------------
__global__ __launch_bounds__(256)
void k_gather_bn(const float* __restrict__ h,
                 const float* __restrict__ gamma, const float* __restrict__ beta,
                 __nv_bfloat16* __restrict__ Hi, __nv_bfloat16* __restrict__ Lo) {
    int gw = (blockIdx.x * 256 + threadIdx.x) >> 5;
    if (gw >= N_NODES * 4) return;
    int lane = threadIdx.x & 31;
    int n = gw >> 2;
    int c = ((gw & 3) << 7) + lane * 4;

    float4 acc = *(const float4*)&h[(size_t)n * D + c];
    int e0 = g_rowptr[n], e1 = g_rowptr[n + 1];
    int e = e0;
    for (; e + 2 <= e1; e += 2) {
        int s0 = g_colidx[e], s1 = g_colidx[e + 1];
        float4 v0 = *(const float4*)&h[(size_t)s0 * D + c];
        float4 v1 = *(const float4*)&h[(size_t)s1 * D + c];
        acc.x += v0.x + v1.x; acc.y += v0.y + v1.y;
        acc.z += v0.z + v1.z; acc.w += v0.w + v1.w;
    }
    if (e < e1) {
        int s0 = g_colidx[e];
        float4 v0 = *(const float4*)&h[(size_t)s0 * D + c];
        acc.x += v0.x; acc.y += v0.y; acc.z += v0.z; acc.w += v0.w;
    }
    float cnt = (float)(e1 - e0 + 1);
    const float invN = 1.0f / N_NODES;
    float4 bs = *(const float4*)&g_bnsum[c];
    float4 bq = *(const float4*)&g_bnsq[c];
    float4 gm = *(const float4*)&gamma[c];
    float4 bt = *(const float4*)&beta[c];
    float m0 = bs.x * invN, m1 = bs.y * invN, m2 = bs.z * invN, m3 = bs.w * invN;
    float s0 = gm.x * rsqrtf(bq.x * invN - m0 * m0 + BN_EPS);
    float s1 = gm.y * rsqrtf(bq.y * invN - m1 * m1 + BN_EPS);
    float s2 = gm.z * rsqrtf(bq.z * invN - m2 * m2 + BN_EPS);
    float s3 = gm.w * rsqrtf(bq.w * invN - m3 * m3 + BN_EPS);
    float4 o;
    o.x = s0 * acc.x + cnt * (bt.x - s0 * m0);
    o.y = s1 * acc.y + cnt * (bt.y - s1 * m1);
    o.z = s2 * acc.z + cnt * (bt.z - s2 * m2);
    o.w = s3 * acc.w + cnt * (bt.w - s3 * m3);
    ull pl;
    ull ph = split_pack4(o, pl);
    *(ull*)&Hi[(size_t)n * D + c] = ph;
    *(ull*)&Lo[(size_t)n * D + c] = pl;
}

// ---------------------------------------------------------------------------
// HMMA GEMM: BM=64, BN=128, BK=32, 128 threads (4 warps, 32x64 warp tile),
// SW64-swizzled smem, cp.async double-buffered, 4 CTAs/SM.
// 3-term split: Ahi*Bhi + Ahi*Blo + Alo*Bhi, fp32 accum.
// mode 0: out f32 + relu + fused BN stats; mode 1: out split bf16 + relu.
// zeroBn (mode-1 only): block (0,0) zeroes BN counters for the NEXT kernel.
// zeroPool (mode-0 only): block (0,0) zeroes pool/cnt for the NEXT kernel.
// ---------------------------------------------------------------------------
#define BM 64
#define BN 128
#define BK 32
#define A_ARR 4096                 // 64 rows * 64 B
#define B_ARR 8192                 // 128 rows * 64 B
#define STG_B (2 * A_ARR + 2 * B_ARR)   // 24576
#define GEMM_SMEM (2 * STG_B)           // 49152

__global__ __launch_bounds__(128, 4)
void k_gemm512_mma(const __nv_bfloat16* __restrict__ Ahi,
                   const __nv_bfloat16* __restrict__ Alo,
                   const __nv_bfloat16* __restrict__ Bthi,
                   const __nv_bfloat16* __restrict__ Btlo,
                   const float* __restrict__ bias,
                   float* __restrict__ Cf,
                   __nv_bfloat16* __restrict__ Chi,
                   __nv_bfloat16* __restrict__ Clo,
                   int M, int mode, int zeroBn, int zeroPool) {
    extern __shared__ char sm[];
    const uint32_t sbase = smem_u32(sm);

    const int tid = threadIdx.x;
    const int lane = tid & 31;
    const int warp = tid >> 5;
    const int wm = warp & 1;       // 2 warps over M (32 rows each)
    const int wn = warp >> 1;      // 2 warps over N (64 cols each)
    const int rowBase = blockIdx.x * BM;
    const int colBase = blockIdx.y * BN;

    if (blockIdx.x == 0 && blockIdx.y == 0) {
        if (zeroBn) {
            ((float4*)g_bnsum)[tid] = make_float4(0.f, 0.f, 0.f, 0.f);
            ((float4*)g_bnsq)[tid] = make_float4(0.f, 0.f, 0.f, 0.f);
        }
        if (zeroPool) {
#pragma unroll
            for (int j = 0; j < 64; j++)
                ((float4*)g_pool)[tid + j * 128] = make_float4(0.f, 0.f, 0.f, 0.f);
            if (tid < N_GRAPHS) g_cnt[tid] = 0.f;
        }
    }

    // producer coords
    const int ra = tid >> 2, ca = tid & 3;            // A: 2 rounds (ra, ra+32)
    const int rb = tid >> 2, cb = tid & 3;            // B: 4 rounds (rb + 32*j)

    float acc[2][8][4];
#pragma unroll
    for (int mi = 0; mi < 2; mi++)
#pragma unroll
        for (int ni = 0; ni < 8; ni++)
#pragma unroll
            for (int j = 0; j < 4; j++) acc[mi][ni][j] = 0.f;

#define PREFETCH(kc_, s_)                                                           \
    {                                                                               \
        const int k0_ = (kc_) * BK;                                                 \
        const uint32_t sb_ = sbase + (s_) * STG_B;                                  \
        _Pragma("unroll")                                                           \
        for (int j_ = 0; j_ < 2; j_++) {                                            \
            int r_ = ra + j_ * 32;                                                  \
            int ok_ = (rowBase + r_ < M) ? 16 : 0;                                  \
            uint32_t so_ = swz((uint32_t)(r_ * 64 + ca * 16));                      \
            cpasync16(sb_ + so_, &Ahi[(size_t)(rowBase + r_) * D + k0_ + ca * 8], ok_); \
            cpasync16(sb_ + A_ARR + so_, &Alo[(size_t)(rowBase + r_) * D + k0_ + ca * 8], ok_); \
        }                                                                           \
        _Pragma("unroll")                                                           \
        for (int j_ = 0; j_ < 4; j_++) {                                            \
            int r_ = rb + j_ * 32;                                                  \
            uint32_t so_ = swz((uint32_t)(r_ * 64 + cb * 16));                      \
            cpasync16(sb_ + 2 * A_ARR + so_, &Bthi[(size_t)(colBase + r_) * D + k0_ + cb * 8], 16); \
            cpasync16(sb_ + 2 * A_ARR + B_ARR + so_, &Btlo[(size_t)(colBase + r_) * D + k0_ + cb * 8], 16); \
        }                                                                           \
        cp_commit();                                                                \
    }

    PREFETCH(0, 0);

    for (int kc = 0; kc < D / BK; kc++) {
        const int s = kc & 1;
        if (kc + 1 < D / BK) {
            PREFETCH(kc + 1, s ^ 1);
            cp_wait1();
        } else {
            cp_wait0();
        }
        __syncthreads();

        const uint32_t sb = sbase + s * STG_B;
        const uint32_t aHiB = sb, aLoB = sb + A_ARR;
        const uint32_t bHiB = sb + 2 * A_ARR, bLoB = bHiB + B_ARR;

#pragma unroll
        for (int ks = 0; ks < 2; ks++) {
            const int kk = ks * 16;
            uint32_t ahi[2][4], alo[2][4];
#pragma unroll
            for (int mi = 0; mi < 2; mi++) {
                int row = wm * 32 + mi * 16 + (lane & 15);
                uint32_t off = swz((uint32_t)(row * 64 + kk * 2 + (lane >> 4) * 16));
                ldsm4(ahi[mi], aHiB + off);
                ldsm4(alo[mi], aLoB + off);
            }
            int brow = wn * 64 + (lane & 7) + ((lane >> 4) << 3);
            int bcolb = kk * 2 + ((lane >> 3) & 1) * 16;
#pragma unroll
            for (int np = 0; np < 4; np++) {
                uint32_t bhi4[4], blo4[4];
                uint32_t off = swz((uint32_t)((brow + np * 16) * 64 + bcolb));
                ldsm4(bhi4, bHiB + off);
                ldsm4(blo4, bLoB + off);
#pragma unroll
                for (int mi = 0; mi < 2; mi++) {
                    mma16816(acc[mi][2 * np + 0], ahi[mi], bhi4 + 0);
                    mma16816(acc[mi][2 * np + 0], ahi[mi], blo4 + 0);
                    mma16816(acc[mi][2 * np + 0], alo[mi], bhi4 + 0);
                    mma16816(acc[mi][2 * np + 1], ahi[mi], bhi4 + 2);
                    mma16816(acc[mi][2 * np + 1], ahi[mi], blo4 + 2);
                    mma16816(acc[mi][2 * np + 1], alo[mi], bhi4 + 2);
                }
            }
        }
        __syncthreads();
    }
#undef PREFETCH

    // ---- epilogue
    if (mode == 0) {
        float* scol = (float*)sm;          // 128 floats
        float* qcol = scol + 128;          // 128 floats
        scol[tid] = 0.f; qcol[tid] = 0.f;
        __syncthreads();
#pragma unroll
        for (int ni = 0; ni < 8; ni++) {
            int col = colBase + wn * 64 + ni * 8 + (lane & 3) * 2;
            float b0 = bias[col], b1 = bias[col + 1];
            float s0 = 0.f, q0 = 0.f, s1 = 0.f, q1 = 0.f;
#pragma unroll
            for (int mi = 0; mi < 2; mi++) {
                int row0 = rowBase + wm * 32 + mi * 16 + (lane >> 2);
                int row1 = row0 + 8;
                float v00 = fmaxf(acc[mi][ni][0] + b0, 0.f);
                float v01 = fmaxf(acc[mi][ni][1] + b1, 0.f);
                float v10 = fmaxf(acc[mi][ni][2] + b0, 0.f);
                float v11 = fmaxf(acc[mi][ni][3] + b1, 0.f);
                if (row0 < M) {
                    *(float2*)&Cf[(size_t)row0 * D + col] = make_float2(v00, v01);
                    s0 += v00; q0 += v00 * v00; s1 += v01; q1 += v01 * v01;
                }
                if (row1 < M) {
                    *(float2*)&Cf[(size_t)row1 * D + col] = make_float2(v10, v11);
                    s0 += v10; q0 += v10 * v10; s1 += v11; q1 += v11 * v11;
                }
            }
#pragma unroll
            for (int o = 4; o < 32; o <<= 1) {
                s0 += __shfl_xor_sync(0xffffffffu, s0, o);
                q0 += __shfl_xor_sync(0xffffffffu, q0, o);
                s1 += __shfl_xor_sync(0xffffffffu, s1, o);
                q1 += __shfl_xor_sync(0xffffffffu, q1, o);
            }
            if (lane < 4) {
                int lc = wn * 64 + ni * 8 + lane * 2;
                atomicAdd(&scol[lc], s0);
                atomicAdd(&qcol[lc], q0);
                atomicAdd(&scol[lc + 1], s1);
                atomicAdd(&qcol[lc + 1], q1);
            }
        }
        __syncthreads();
        atomicAdd(&g_bnsum[colBase + tid], scol[tid]);
        atomicAdd(&g_bnsq[colBase + tid], qcol[tid]);
    } else {
#pragma unroll
        for (int mi = 0; mi < 2; mi++) {
            int row0 = rowBase + wm * 32 + mi * 16 + (lane >> 2);
            int row1 = row0 + 8;
#pragma unroll
            for (int ni = 0; ni < 8; ni++) {
                int col = colBase + wn * 64 + ni * 8 + (lane & 3) * 2;
                float b0 = bias[col], b1 = bias[col + 1];
                float v00 = fmaxf(acc[mi][ni][0] + b0, 0.f);
                float v01 = fmaxf(acc[mi][ni][1] + b1, 0.f);
                float v10 = fmaxf(acc[mi][ni][2] + b0, 0.f);
                float v11 = fmaxf(acc[mi][ni][3] + b1, 0.f);
                __nv_bfloat16 h0 = __float2bfloat16(v00), h1 = __float2bfloat16(v01);
                __nv_bfloat16 h2 = __float2bfloat16(v10), h3 = __float2bfloat16(v11);
                __nv_bfloat16 l0 = __float2bfloat16(v00 - __bfloat162float(h0));
                __nv_bfloat16 l1 = __float2bfloat16(v01 - __bfloat162float(h1));
                __nv_bfloat16 l2 = __float2bfloat16(v10 - __bfloat162float(h2));
                __nv_bfloat16 l3 = __float2bfloat16(v11 - __bfloat162float(h3));
                if (row0 < M) {
                    *(uint32_t*)&Chi[(size_t)row0 * D + col] =
                        (uint32_t)__bfloat16_as_ushort(h0) | ((uint32_t)__bfloat16_as_ushort(h1) << 16);
                    *(uint32_t*)&Clo[(size_t)row0 * D + col] =
                        (uint32_t)__bfloat16_as_ushort(l0) | ((uint32_t)__bfloat16_as_ushort(l1) << 16);
                }
                if (row1 < M) {
                    *(uint32_t*)&Chi[(size_t)row1 * D + col] =
                        (uint32_t)__bfloat16_as_ushort(h2) | ((uint32_t)__bfloat16_as_ushort(h3) << 16);
                    *(uint32_t*)&Clo[(size_t)row1 * D + col] =
                        (uint32_t)__bfloat16_as_ushort(l2) | ((uint32_t)__bfloat16_as_ushort(l3) << 16);
                }
            }
        }
    }
}

// ---------------------------------------------------------------------------
// Pool + head (BN affine applied to pooled means inside k_head)
// ---------------------------------------------------------------------------
__global__ void k_poolscatter(const float* __restrict__ h, const int* __restrict__ batch) {
    int idx = blockIdx.x * blockDim.x + threadIdx.x;
    if (idx >= N_NODES * (D / 4)) return;
    int n = idx >> 7;
    int g = (idx & 127) << 2;
    int b = batch[n];
    float4 v = *(const float4*)&h[n * D + g];
    red_add_v4(&g_pool[b * D + g], v);
    if ((idx & 127) == 0) atomicAdd(&g_cnt[b], 1.0f);
}
__global__ void k_head(const float* __restrict__ Wfc, const float* __restrict__ bfc,
                       const float* __restrict__ Wlog, const float* __restrict__ blog,
                       const float* __restrict__ gamma, const float* __restrict__ beta,
                       float* __restrict__ out) {
    __shared__ float sp[D];
    __shared__ float sf[D];
    int g = blockIdx.x;
    int t = threadIdx.x;
    float cnt = g_cnt[g];
    float invc = 1.0f / fmaxf(cnt, 1.0f);
    const float invN = 1.0f / N_NODES;
    float mean = g_bnsum[t] * invN;
    float var = g_bnsq[t] * invN - mean * mean;
    float sc = gamma[t] * rsqrtf(var + BN_EPS);
    sp[t] = sc * (g_pool[g * D + t] * invc) + (cnt * invc) * (beta[t] - sc * mean);
    __syncthreads();
    float f = bfc[t];
    for (int k = 0; k < D; k++) f += sp[k] * Wfc[k * D + t];
    sf[t] = tanhf(f);
    __syncthreads();
    if (t < N_OUT) {
        float l = blog[t];
        for (int k = 0; k < D; k++) l += sf[k] * Wlog[k * N_OUT + t];
        out[g * N_OUT + t] = l;
    }
}

// ---------------------------------------------------------------------------
// Launcher
// ---------------------------------------------------------------------------
extern "C" void kernel_launch(void* const* d_in, const int* in_sizes, int n_in,
                              void* d_out, int out_size) {
    const float* x     = (const float*)d_in[0];
    const int*   ei    = (const int*)d_in[1];
    const int*   batch = (const int*)d_in[2];
    const float* W1a   = (const float*)d_in[3];
    const float* b1a   = (const float*)d_in[4];
    const float* W1b   = (const float*)d_in[5];
    const float* b1b   = (const float*)d_in[6];
    const float* Wa    = (const float*)d_in[7];
    const float* ba    = (const float*)d_in[8];
    const float* Wb    = (const float*)d_in[9];
    const float* bb    = (const float*)d_in[10];
    const float* bn_g  = (const float*)d_in[11];
    const float* bn_b  = (const float*)d_in[12];
    const float* Wfc   = (const float*)d_in[13];
    const float* bfc   = (const float*)d_in[14];
    const float* Wlog  = (const float*)d_in[15];
    const float* blog  = (const float*)d_in[16];
    float* out = (float*)d_out;

    const int* src = ei;
    const int* dst = ei + N_EDGES;

    float *h, *agg16;
    __nv_bfloat16 *whi, *wlo, *thi, *tlo, *ahi, *alo;
    cudaGetSymbolAddress((void**)&h,     g_h);
    cudaGetSymbolAddress((void**)&agg16, g_agg16);
    cudaGetSymbolAddress((void**)&whi,   g_Whi);
    cudaGetSymbolAddress((void**)&wlo,   g_Wlo);
    cudaGetSymbolAddress((void**)&thi,   g_tHi);
    cudaGetSymbolAddress((void**)&tlo,   g_tLo);
    cudaGetSymbolAddress((void**)&ahi,   g_aHi);
    cudaGetSymbolAddress((void**)&alo,   g_aLo);

    cudaFuncSetAttribute(k_gemm512_mma, cudaFuncAttributeMaxDynamicSharedMemorySize, GEMM_SMEM);

    const int TB = 256;
    dim3 gemmGrid((N_NODES + BM - 1) / BM, D / BN);   // (157, 4)
    const size_t DD = (size_t)D * D;

    // CSR build + weight pre-convert
    k_zero_deg<<<(N_NODES + TB - 1) / TB, TB>>>();
    k_deg<<<(N_EDGES + TB - 1) / TB, TB>>>(dst);
    k_scan<<<1, 1024>>>();
    k_fill<<<(N_EDGES + TB - 1) / TB, TB>>>(src, dst);
    k_convW<<<dim3(16, 16, 9), dim3(32, 8)>>>(W1b, Wa, Wb);

    // ---- layer 1 ----
    k_copy4<<<(N_NODES * IN_F / 4 + TB - 1) / TB, TB>>>(agg16, x, N_NODES * IN_F / 4);
    k_scatter16<<<(N_EDGES * 4 + TB - 1) / TB, TB>>>(x, src, dst);
    k_gemm16<<<(N_NODES * 128 + TB - 1) / TB, TB>>>(W1a, b1a);   // also zeroes BN counters
    k_gemm512_mma<<<gemmGrid, 128, GEMM_SMEM>>>(thi, tlo, whi, wlo, b1b, h,
                                                ((__nv_bfloat16*)0), ((__nv_bfloat16*)0),
                                                N_NODES, 0, 0, 0);

    // ---- layers 2..5 ----
    for (int i = 0; i < 4; i++) {
        k_gather_bn<<<(N_NODES * 4 * 32 + TB - 1) / TB, TB>>>(h, bn_g + i * D, bn_b + i * D,
                                                              ahi, alo);
        // mode-1 GEMM zeroes BN counters for the following mode-0 GEMM
        k_gemm512_mma<<<gemmGrid, 128, GEMM_SMEM>>>(ahi, alo,
                                                    whi + (size_t)(1 + 2 * i) * DD,
                                                    wlo + (size_t)(1 + 2 * i) * DD,
                                                    ba + i * D, ((float*)0), thi, tlo,
                                                    N_NODES, 1, 1, 0);
        // last mode-0 GEMM zeroes pool/cnt for the following poolscatter
        k_gemm512_mma<<<gemmGrid, 128, GEMM_SMEM>>>(thi, tlo,
                                                    whi + (size_t)(2 + 2 * i) * DD,
                                                    wlo + (size_t)(2 + 2 * i) * DD,
                                                    bb + i * D, h,
                                                    ((__nv_bfloat16*)0), ((__nv_bfloat16*)0),
                                                    N_NODES, 0, 0, (i == 3) ? 1 : 0);
    }

    // ---- pooling + head (BN5 applied on pooled means) ----
    k_poolscatter<<<(N_NODES * 128 + TB - 1) / TB, TB>>>(h, batch);
    k_head<<<N_GRAPHS, D>>>(Wfc, bfc, Wlog, blog, bn_g + 4 * D, bn_b + 4 * D, out);
}